// round 1
// baseline (speedup 1.0000x reference)
#include <cuda_runtime.h>

// ---------------- problem constants ----------------
#define MB    32          // batch
#define DCH   256         // channels
#define SSP   3136        // 56*56 spatial
#define NGRP  16          // groups
#define GS    16          // group size (channels per group)
#define NSAMP (MB*SSP)    // 100352 samples per channel
#define EPSV  1e-6f

#define TILE      112                 // samples per smem tile (3136/112 = 28 exact)
#define TPI       28                  // tiles per image
#define TILES_TOT (MB*TPI)            // 896 tiles per group
#define STAT_TPB  16                  // tiles per stats block
#define STAT_BLK  (TILES_TOT/STAT_TPB)// 56 blocks per group
#define WHT_TPB   8                   // tiles per whiten block
#define WHT_BLK   (TILES_TOT/WHT_TPB) // 112 blocks per group

// ---------------- scratch (no allocations allowed) ----------------
__device__ float  g_P[NGRP][GS][GS];      // raw product sums  sum x_i x_j
__device__ float  g_S[NGRP][GS];          // raw channel sums
__device__ float2 g_W2[NGRP][GS][GS];     // whitening matrix, packed (w,w)
__device__ float  g_bias[NGRP][GS];       // -W @ mu

// ---------------- f32x2 helpers (sm_100+ packed fp32) ----------------
__device__ __forceinline__ unsigned long long ffma2(unsigned long long a,
                                                    unsigned long long b,
                                                    unsigned long long c) {
    unsigned long long d;
    asm("fma.rn.f32x2 %0, %1, %2, %3;" : "=l"(d) : "l"(a), "l"(b), "l"(c));
    return d;
}
__device__ __forceinline__ unsigned long long pack2(float lo, float hi) {
    unsigned long long r;
    asm("mov.b64 %0, {%1, %2};" : "=l"(r) : "f"(lo), "f"(hi));
    return r;
}
__device__ __forceinline__ void unpack2(unsigned long long v, float& lo, float& hi) {
    asm("mov.b64 {%0, %1}, %2;" : "=f"(lo), "=f"(hi) : "l"(v));
}

// ---------------- kernel 0: zero the scratch accumulators ----------------
__global__ void zero_kernel() {
    int tid = blockIdx.x * 256 + threadIdx.x;
    if (tid < NGRP * GS * GS) ((float*)g_P)[tid] = 0.0f;
    if (tid < NGRP * GS)      ((float*)g_S)[tid] = 0.0f;
}

// ---------------- kernel 1: per-group raw sums and product sums ----------------
// Block: 256 threads = 16 sample-pair slots x 16 (4x4) tiles of the 16x16 matrix.
// Each thread accumulates a 4x4 sub-tile over f32x2 sample pairs.
__global__ __launch_bounds__(256) void stats_kernel(const float* __restrict__ x) {
    __shared__ float sm[GS][TILE];     // channel-major sample tile
    __shared__ float sP[GS][GS];
    __shared__ float sS[GS];

    const int g   = blockIdx.y;
    const int tid = threadIdx.x;
    const int tileTid = tid & 15;
    const int ti = tileTid >> 2;       // row tile  (i = 4*ti + r)
    const int tj = tileTid & 3;        // col tile  (j = 4*tj + c)
    const int slot = tid >> 4;         // sample-pair slot 0..15

    if (tid < GS) sS[tid] = 0.0f;
    sP[tid >> 4][tid & 15] = 0.0f;

    unsigned long long acc[4][4];
#pragma unroll
    for (int r = 0; r < 4; r++)
#pragma unroll
        for (int c = 0; c < 4; c++) acc[r][c] = 0ull;

    float csum[7];
#pragma unroll
    for (int it = 0; it < 7; it++) csum[it] = 0.0f;

    const int c0 = g * GS;

    for (int tt = 0; tt < STAT_TPB; tt++) {
        const int tileId = blockIdx.x * STAT_TPB + tt;
        const int b  = tileId / TPI;
        const int s0 = (tileId - b * TPI) * TILE;
        const float* base = x + ((size_t)b * DCH + c0) * SSP + s0;

        __syncthreads();   // previous tile's compute done before overwrite
#pragma unroll
        for (int it = 0; it < 7; it++) {
            int idx = it * 256 + tid;          // 0..1791 over 16*112 elements
            int c = idx / TILE;
            int t = idx - c * TILE;
            float v = base[(size_t)c * SSP + t];
            sm[c][t] = v;
            csum[it] += v;
        }
        __syncthreads();

        // compute: f32x2 over sample pairs
        for (int pp = slot; pp < TILE / 2; pp += 16) {
            const int t = 2 * pp;
            unsigned long long xi[4], xj[4];
#pragma unroll
            for (int r = 0; r < 4; r++)
                xi[r] = *(const unsigned long long*)&sm[ti * 4 + r][t];
#pragma unroll
            for (int c = 0; c < 4; c++)
                xj[c] = *(const unsigned long long*)&sm[tj * 4 + c][t];
#pragma unroll
            for (int r = 0; r < 4; r++)
#pragma unroll
                for (int c = 0; c < 4; c++)
                    acc[r][c] = ffma2(xi[r], xj[c], acc[r][c]);
        }
    }
    __syncthreads();

    // reduce 16 slots -> shared, then one global atomic per entry per block
#pragma unroll
    for (int r = 0; r < 4; r++)
#pragma unroll
        for (int c = 0; c < 4; c++) {
            float lo, hi;
            unpack2(acc[r][c], lo, hi);
            atomicAdd(&sP[ti * 4 + r][tj * 4 + c], lo + hi);
        }
#pragma unroll
    for (int it = 0; it < 7; it++) {
        int idx = it * 256 + tid;
        int c = idx / TILE;
        atomicAdd(&sS[c], csum[it]);
    }
    __syncthreads();

    atomicAdd(&g_P[g][tid >> 4][tid & 15], sP[tid >> 4][tid & 15]);
    if (tid < GS) atomicAdd(&g_S[g][tid], sS[tid]);
}

// ---------------- kernel 2: sigma -> Cholesky -> inv(T) (one warp per group) ----
__global__ void solve_kernel() {
    __shared__ float A[NGRP][GS][GS + 1];
    __shared__ float Wm[NGRP][GS][GS + 1];
    __shared__ float mu[NGRP][GS];

    const int g    = threadIdx.x >> 5;
    const int lane = threadIdx.x & 31;

    const float invn  = 1.0f / (float)NSAMP;
    const float scale = (1.0f - EPSV) / (float)(NSAMP - 1);

    if (lane < GS) mu[g][lane] = g_S[g][lane] * invn;
    __syncwarp();

    if (lane < GS) {
        const int j = lane;
        const float muj = mu[g][j];
        for (int i = 0; i < GS; i++) {
            float v = (g_P[g][i][j] - (float)NSAMP * mu[g][i] * muj) * scale;
            if (i == j) v += EPSV;
            A[g][i][j] = v;
        }
    }
    __syncwarp();

    // in-place Cholesky (lower), column k at a time, lanes = rows
    for (int k = 0; k < GS; k++) {
        float s = 0.0f;
        if (lane < GS && lane >= k) {
            s = A[g][lane][k];
            for (int p = 0; p < k; p++) s -= A[g][lane][p] * A[g][k][p];
        }
        float d = __shfl_sync(0xffffffffu, s, k);
        d = sqrtf(d);
        if (lane < GS && lane >= k)
            A[g][lane][k] = (lane == k) ? d : s / d;
        __syncwarp();
    }

    // invert lower triangular: T * W = I, lanes = columns
    if (lane < GS) {
        const int c = lane;
        for (int r = 0; r < GS; r++) Wm[g][r][c] = 0.0f;
        Wm[g][c][c] = 1.0f / A[g][c][c];
        for (int r = c + 1; r < GS; r++) {
            float t = 0.0f;
            for (int p = c; p < r; p++) t += A[g][r][p] * Wm[g][p][c];
            Wm[g][r][c] = -t / A[g][r][r];
        }
    }
    __syncwarp();

    // emit packed W rows and bias = -W @ mu
    if (lane < GS) {
        const int i = lane;
        float bias = 0.0f;
        for (int j = 0; j < GS; j++) {
            float w = Wm[g][i][j];
            bias -= w * mu[g][j];
            g_W2[g][i][j] = make_float2(w, w);
        }
        g_bias[g][i] = bias;
    }
}

// ---------------- kernel 3: apply whitening ----------------
// Block: 256 threads = 16 output channels x 16 sample-pair slots. W row lives
// in 32 registers; x tile staged in smem; f32x2 matvec; 8B stores.
__global__ __launch_bounds__(256) void whiten_kernel(const float* __restrict__ x,
                                                     float* __restrict__ out) {
    __shared__ float sm[GS][TILE];

    const int g    = blockIdx.y;
    const int tid  = threadIdx.x;
    const int i    = tid >> 4;        // output channel within group
    const int slot = tid & 15;

    unsigned long long w2[GS];
#pragma unroll
    for (int j = 0; j < GS; j++)
        w2[j] = *(const unsigned long long*)&g_W2[g][i][j];
    const float bias = g_bias[g][i];
    const unsigned long long bias2 = pack2(bias, bias);

    const int c0 = g * GS;

    for (int tt = 0; tt < WHT_TPB; tt++) {
        const int tileId = blockIdx.x * WHT_TPB + tt;
        const int b  = tileId / TPI;
        const int s0 = (tileId - b * TPI) * TILE;
        const float* base  = x   + ((size_t)b * DCH + c0) * SSP + s0;
        float*       obase = out + ((size_t)b * DCH + c0) * SSP + s0;

        __syncthreads();
#pragma unroll
        for (int it = 0; it < 7; it++) {
            int idx = it * 256 + tid;
            int c = idx / TILE;
            int t = idx - c * TILE;
            sm[c][t] = base[(size_t)c * SSP + t];
        }
        __syncthreads();

        for (int pp = slot; pp < TILE / 2; pp += 16) {
            const int t = 2 * pp;
            unsigned long long acc = bias2;
#pragma unroll
            for (int j = 0; j < GS; j++) {
                unsigned long long xj = *(const unsigned long long*)&sm[j][t];
                acc = ffma2(w2[j], xj, acc);
            }
            *(unsigned long long*)&obase[(size_t)i * SSP + t] = acc;
        }
    }
}

// ---------------- launch ----------------
extern "C" void kernel_launch(void* const* d_in, const int* in_sizes, int n_in,
                              void* d_out, int out_size) {
    const float* x = (const float*)d_in[0];
    float* out = (float*)d_out;

    zero_kernel<<<16, 256>>>();

    dim3 sgrid(STAT_BLK, NGRP);            // 56 x 16 = 896 blocks
    stats_kernel<<<sgrid, 256>>>(x);

    solve_kernel<<<1, 512>>>();            // one warp per group

    dim3 wgrid(WHT_BLK, NGRP);             // 112 x 16 = 1792 blocks
    whiten_kernel<<<wgrid, 256>>>(x, out);
}